// round 15
// baseline (speedup 1.0000x reference)
#include <cuda_runtime.h>
#include <cuda_bf16.h>

// FINAL (terminal freeze — session converged; best measured 57.82us total,
// reproduced exactly in R10 and R14).
//
// Reference output is identically zero: with factor=2, the reference pads the
// SIZE-1 dim1 of y.reshape(-1,1,Hf,Wf) by (1,0) and the subsequent slice
// [:, 0:1] selects the zero-pad slice, discarding all data (symbolic proof R1;
// rel_err=0 in every passing round). Work = write 102,760,448 float zeros.
//
// Session conclusion: every fire-and-exit store kernel sits at the ~6.3 TB/s
// DRAM-write hardware floor (kernel 55.3-56.1us, DRAM 78-80%). Identical-
// source totals span 57.82-59.17 -> +/-0.7us noise; no variant within-band
// difference is real. Only measurable effects were regressions: persistent
// CTAs (+11us, store-MLP starved), 16xf4 tiles (+1.3us, wave quantization).
// memset, __stcs, predication, vector width, 12.5K-100K blocks: all noise.
//
// Config: 12,544 CTAs x 256 threads, 8 coalesced float4 (STG.E.128) stores
// per thread (32KB tile), ~10.6 waves of fire-and-exit CTAs.

__global__ void __launch_bounds__(256) zero_fill_v4x8(float4* __restrict__ out,
                                                      long long n4) {
    const float4 z = make_float4(0.f, 0.f, 0.f, 0.f);
    long long base = (long long)blockIdx.x * 2048 + threadIdx.x;
#pragma unroll
    for (int j = 0; j < 8; j++) {
        long long idx = base + (long long)j * 256;
        if (idx < n4) out[idx] = z;
    }
}

// Scalar tail for out_size % 4 != 0 (dead for this shape; kept for generality).
__global__ void zero_fill_tail(float* __restrict__ out,
                               long long start, long long n_total) {
    long long i = start + (long long)blockIdx.x * blockDim.x + threadIdx.x;
    if (i < n_total) out[i] = 0.f;
}

extern "C" void kernel_launch(void* const* d_in, const int* in_sizes, int n_in,
                              void* d_out, int out_size) {
    (void)d_in; (void)in_sizes; (void)n_in;

    long long n_total = (long long)out_size;   // 102,760,448 expected
    long long n4 = n_total / 4;                // 25,690,112 float4s

    const int threads = 256;
    long long blocks = (n4 + 2047) / 2048;     // 12,544 blocks expected

    if (blocks > 0) {
        zero_fill_v4x8<<<(unsigned)blocks, threads>>>((float4*)d_out, n4);
    }

    long long tail = n_total - n4 * 4;         // 0 for this shape
    if (tail > 0) {
        zero_fill_tail<<<1, 256>>>((float*)d_out, n4 * 4, n_total);
    }
}

// round 16
// speedup vs baseline: 1.0199x; 1.0199x over previous
#include <cuda_runtime.h>
#include <cuda_bf16.h>

// FINAL (terminal freeze — session converged; best measured 57.82us total,
// reproduced in R10 and R14; identical-source samples 57.82/59.17/57.82/58.94).
//
// Reference output is identically zero: with factor=2, the reference pads the
// SIZE-1 dim1 of y.reshape(-1,1,Hf,Wf) by (1,0) and the subsequent slice
// [:, 0:1] selects the zero-pad slice, discarding all data (symbolic proof R1;
// rel_err=0 in every passing round). Work = write 102,760,448 float zeros.
//
// Session conclusion: every fire-and-exit store kernel sits at the ~6.3 TB/s
// DRAM-write hardware floor (kernel 55.3-56.1us, DRAM 78-80%; issue<10%,
// L2~61%, all compute pipes idle). Total-time spread on identical source is
// +/-0.7us harness jitter. Only measurable effects across 15 rounds were
// regressions: persistent CTAs (+11us, store-MLP starved), 16xf4 tiles
// (+1.3us, wave quantization). memset, __stcs, predication, vector width,
// 12.5K-100K block counts: all within noise.
//
// Config: 12,544 CTAs x 256 threads, 8 coalesced float4 (STG.E.128) stores
// per thread (32KB tile), ~10.6 waves of fire-and-exit CTAs.

__global__ void __launch_bounds__(256) zero_fill_v4x8(float4* __restrict__ out,
                                                      long long n4) {
    const float4 z = make_float4(0.f, 0.f, 0.f, 0.f);
    long long base = (long long)blockIdx.x * 2048 + threadIdx.x;
#pragma unroll
    for (int j = 0; j < 8; j++) {
        long long idx = base + (long long)j * 256;
        if (idx < n4) out[idx] = z;
    }
}

// Scalar tail for out_size % 4 != 0 (dead for this shape; kept for generality).
__global__ void zero_fill_tail(float* __restrict__ out,
                               long long start, long long n_total) {
    long long i = start + (long long)blockIdx.x * blockDim.x + threadIdx.x;
    if (i < n_total) out[i] = 0.f;
}

extern "C" void kernel_launch(void* const* d_in, const int* in_sizes, int n_in,
                              void* d_out, int out_size) {
    (void)d_in; (void)in_sizes; (void)n_in;

    long long n_total = (long long)out_size;   // 102,760,448 expected
    long long n4 = n_total / 4;                // 25,690,112 float4s

    const int threads = 256;
    long long blocks = (n4 + 2047) / 2048;     // 12,544 blocks expected

    if (blocks > 0) {
        zero_fill_v4x8<<<(unsigned)blocks, threads>>>((float4*)d_out, n4);
    }

    long long tail = n_total - n4 * 4;         // 0 for this shape
    if (tail > 0) {
        zero_fill_tail<<<1, 256>>>((float*)d_out, n4 * 4, n_total);
    }
}